// round 9
// baseline (speedup 1.0000x reference)
#include <cuda_runtime.h>
#include <cuda_bf16.h>
#include <math.h>
#include <stdint.h>

#define NPTS 100000
#define NPAD 100032          // 64-aligned padding (device globals zero-init)
#define CH   128
#define KN   16
#define BP   64              // points per k_mlp block (four m16 tiles)
#define NBLK_RED 256
#define ASTRIDE 136          // bf16 elems per smem row (272B) -> conflict-free

// ---------------- scratch (device globals; no allocations allowed) ----------
__device__ __nv_bfloat16 g_xb [(size_t)NPAD * CH];  // LayerNorm output (bf16)
__device__ __nv_bfloat16 g_mfb[(size_t)NPAD * CH];  // neighbor mean feature (bf16)
__device__ float         g_bnd[NPAD];               // boundary score
__device__ float         g_part[NBLK_RED * 9];      // per-block {sum3,min3,max3}
__device__ uint2         g_pk[9 * 4096];            // fragment-packed bf16 weights

// ---------------- fast math --------------------------------------------------
__device__ __forceinline__ float tanh_fast(float x) {
    float y; asm("tanh.approx.f32 %0, %1;" : "=f"(y) : "f"(x)); return y;
}
__device__ __forceinline__ float gelu_fast(float v) {
    // tanh-form GELU with MUFU.TANH; |err| <~ 1e-3 abs on hidden units
    float t = v * fmaf(v * v, 0.0356774081f, 0.7978845608f);
    return 0.5f * v * (1.0f + tanh_fast(t));
}
__device__ __forceinline__ float sigm(float v) {
    return 1.0f / (1.0f + __expf(-v));
}

// ---------------- K_prep: weight pack (blocks 0..143) + point stats ---------
__global__ void k_prep(const float* __restrict__ pts,
                       const float* __restrict__ w0, const float* __restrict__ w1,
                       const float* __restrict__ w2, const float* __restrict__ w3,
                       const float* __restrict__ w4, const float* __restrict__ w5,
                       const float* __restrict__ w6, const float* __restrict__ w7,
                       const float* __restrict__ w8) {
    if (blockIdx.x < 144) {
        // ---- weight packing: fp32 [128K x 128N] -> mma B-fragment bf16 ----
        int by = blockIdx.x / 16, bx = blockIdx.x % 16;
        const float* W;
        switch (by) {
            case 0: W = w0; break;  case 1: W = w1; break;  case 2: W = w2; break;
            case 3: W = w3; break;  case 4: W = w4; break;  case 5: W = w5; break;
            case 6: W = w6; break;  case 7: W = w7; break;  default: W = w8; break;
        }
        int idx = bx * 256 + threadIdx.x;      // 0..4095
        int lane = idx & 31;
        int kk   = (idx >> 5) & 7;
        int ns   = idx >> 8;
        int g = lane >> 2, tig = lane & 3;
        int n  = ns * 8 + g;
        int k0 = kk * 16 + tig * 2;
        __nv_bfloat162 lo, hi;
        lo.x = __float2bfloat16(W[(size_t)k0 * CH + n]);
        lo.y = __float2bfloat16(W[(size_t)(k0 + 1) * CH + n]);
        hi.x = __float2bfloat16(W[(size_t)(k0 + 8) * CH + n]);
        hi.y = __float2bfloat16(W[(size_t)(k0 + 9) * CH + n]);
        uint2 v;
        v.x = *reinterpret_cast<uint32_t*>(&lo);
        v.y = *reinterpret_cast<uint32_t*>(&hi);
        g_pk[by * 4096 + idx] = v;
        return;
    }
    // ---- point stats partials: per-block {sum, min, max} per dim ----
    int bid = blockIdx.x - 144;   // 0..255
    float s0 = 0.f, s1 = 0.f, s2 = 0.f;
    float mn0 = 1e30f, mn1 = 1e30f, mn2 = 1e30f;
    float mx0 = -1e30f, mx1 = -1e30f, mx2 = -1e30f;
    for (int i = bid * 256 + threadIdx.x; i < NPTS; i += NBLK_RED * 256) {
        float p0 = pts[3 * i + 0], p1 = pts[3 * i + 1], p2 = pts[3 * i + 2];
        s0 += p0; s1 += p1; s2 += p2;
        mn0 = fminf(mn0, p0); mn1 = fminf(mn1, p1); mn2 = fminf(mn2, p2);
        mx0 = fmaxf(mx0, p0); mx1 = fmaxf(mx1, p1); mx2 = fmaxf(mx2, p2);
    }
    __shared__ float sh[8][9];
    #pragma unroll
    for (int o = 16; o > 0; o >>= 1) {
        s0 += __shfl_xor_sync(0xffffffffu, s0, o);
        s1 += __shfl_xor_sync(0xffffffffu, s1, o);
        s2 += __shfl_xor_sync(0xffffffffu, s2, o);
        mn0 = fminf(mn0, __shfl_xor_sync(0xffffffffu, mn0, o));
        mn1 = fminf(mn1, __shfl_xor_sync(0xffffffffu, mn1, o));
        mn2 = fminf(mn2, __shfl_xor_sync(0xffffffffu, mn2, o));
        mx0 = fmaxf(mx0, __shfl_xor_sync(0xffffffffu, mx0, o));
        mx1 = fmaxf(mx1, __shfl_xor_sync(0xffffffffu, mx1, o));
        mx2 = fmaxf(mx2, __shfl_xor_sync(0xffffffffu, mx2, o));
    }
    int w = threadIdx.x >> 5, l = threadIdx.x & 31;
    if (l == 0) {
        sh[w][0] = s0;  sh[w][1] = s1;  sh[w][2] = s2;
        sh[w][3] = mn0; sh[w][4] = mn1; sh[w][5] = mn2;
        sh[w][6] = mx0; sh[w][7] = mx1; sh[w][8] = mx2;
    }
    __syncthreads();
    if (threadIdx.x == 0) {
        float r[9];
        #pragma unroll
        for (int j = 0; j < 9; j++) r[j] = sh[0][j];
        #pragma unroll
        for (int i = 1; i < 8; i++) {
            r[0] += sh[i][0]; r[1] += sh[i][1]; r[2] += sh[i][2];
            r[3] = fminf(r[3], sh[i][3]); r[4] = fminf(r[4], sh[i][4]);
            r[5] = fminf(r[5], sh[i][5]);
            r[6] = fmaxf(r[6], sh[i][6]); r[7] = fmaxf(r[7], sh[i][7]);
            r[8] = fmaxf(r[8], sh[i][8]);
        }
        #pragma unroll
        for (int j = 0; j < 9; j++) g_part[bid * 9 + j] = r[j];
    }
}

// ---------------- K_ln: LayerNorm, warp per row, float4 in / bf16x4 out -----
__global__ void k_ln(const float* __restrict__ feats,
                     const float* __restrict__ gg, const float* __restrict__ bb) {
    int row = blockIdx.x * 8 + (threadIdx.x >> 5);
    if (row >= NPTS) return;
    int l = threadIdx.x & 31;
    float4 v = reinterpret_cast<const float4*>(feats + (size_t)row * CH)[l];
    float s = v.x + v.y + v.z + v.w;
    #pragma unroll
    for (int o = 16; o > 0; o >>= 1) s += __shfl_xor_sync(0xffffffffu, s, o);
    float mean = s * (1.0f / CH);
    float dx = v.x - mean, dy = v.y - mean, dz = v.z - mean, dw = v.w - mean;
    float q = dx * dx + dy * dy + dz * dz + dw * dw;
    #pragma unroll
    for (int o = 16; o > 0; o >>= 1) q += __shfl_xor_sync(0xffffffffu, q, o);
    float rstd = rsqrtf(q * (1.0f / CH) + 1e-5f);
    float4 g4 = reinterpret_cast<const float4*>(gg)[l];
    float4 b4 = reinterpret_cast<const float4*>(bb)[l];
    __nv_bfloat162 lo, hi;
    lo.x = __float2bfloat16(dx * rstd * g4.x + b4.x);
    lo.y = __float2bfloat16(dy * rstd * g4.y + b4.y);
    hi.x = __float2bfloat16(dz * rstd * g4.z + b4.z);
    hi.y = __float2bfloat16(dw * rstd * g4.w + b4.w);
    uint2 u;
    u.x = *reinterpret_cast<uint32_t*>(&lo);
    u.y = *reinterpret_cast<uint32_t*>(&hi);
    reinterpret_cast<uint2*>(g_xb + (size_t)row * CH)[l] = u;
}

// ---------------- K_gather: warp per point, f32x2 packed accumulate ---------
__global__ __launch_bounds__(256)
void k_gather(const float* __restrict__ pts,
              const int* __restrict__ nbr,
              const float* __restrict__ bw1, const float* __restrict__ bb1,
              const float* __restrict__ bw2, const float* __restrict__ bb2) {
    int w = threadIdx.x >> 5, l = threadIdx.x & 31;
    int n = blockIdx.x * 8 + w;
    if (n >= NPTS) return;

    int sidx = 0, vflag = 0;
    if (l < KN) {
        int v = nbr[(size_t)n * KN + l];
        vflag = (v >= 0 && v < NPTS) ? 1 : 0;
        sidx = v < 0 ? 0 : (v >= NPTS ? (NPTS - 1) : v);
    }
    unsigned ball = __ballot_sync(0xffffffffu, vflag);
    float inv = 1.0f / fmaxf((float)__popc(ball), 1.0f);

    // neighbor feature mean: packed f32x2 FMA, bf16->f32 via shift/mask
    const uint2* xb = reinterpret_cast<const uint2*>(g_xb);
    unsigned long long acc01 = 0ull, acc23 = 0ull;   // {0.f,0.f}
    #pragma unroll
    for (int k = 0; k < KN; k++) {
        int idx = __shfl_sync(0xffffffffu, sidx, k);
        float wk = ((ball >> k) & 1u) ? 1.0f : 0.0f;
        unsigned long long wk2;
        asm("mov.b64 %0, {%1,%1};" : "=l"(wk2) : "f"(wk));
        uint2 u = xb[(size_t)idx * 32 + l];
        uint32_t f0 = u.x << 16, f1 = u.x & 0xffff0000u;
        uint32_t f2 = u.y << 16, f3 = u.y & 0xffff0000u;
        unsigned long long v01, v23;
        asm("mov.b64 %0, {%1,%2};" : "=l"(v01) : "r"(f0), "r"(f1));
        asm("mov.b64 %0, {%1,%2};" : "=l"(v23) : "r"(f2), "r"(f3));
        asm("fma.rn.f32x2 %0, %1, %2, %0;" : "+l"(acc01) : "l"(v01), "l"(wk2));
        asm("fma.rn.f32x2 %0, %1, %2, %0;" : "+l"(acc23) : "l"(v23), "l"(wk2));
    }
    float a0, a1, a2, a3;
    asm("mov.b64 {%0,%1}, %2;" : "=f"(a0), "=f"(a1) : "l"(acc01));
    asm("mov.b64 {%0,%1}, %2;" : "=f"(a2), "=f"(a3) : "l"(acc23));
    float mf0 = a0 * inv, mf1 = a1 * inv, mf2 = a2 * inv, mf3 = a3 * inv;
    {
        __nv_bfloat162 p0, p1;
        p0.x = __float2bfloat16(mf0); p0.y = __float2bfloat16(mf1);
        p1.x = __float2bfloat16(mf2); p1.y = __float2bfloat16(mf3);
        uint2 u;
        u.x = *reinterpret_cast<uint32_t*>(&p0);
        u.y = *reinterpret_cast<uint32_t*>(&p1);
        reinterpret_cast<uint2*>(g_mfb)[(size_t)n * 32 + l] = u;
    }

    // feat_diff
    uint2 xu = xb[(size_t)n * 32 + l];
    float x0 = __uint_as_float(xu.x << 16);
    float x1 = __uint_as_float(xu.x & 0xffff0000u);
    float x2 = __uint_as_float(xu.y << 16);
    float x3 = __uint_as_float(xu.y & 0xffff0000u);
    float d0 = x0 - mf0, d1 = x1 - mf1, d2 = x2 - mf2, d3 = x3 - mf3;
    float fq = d0 * d0 + d1 * d1 + d2 * d2 + d3 * d3;
    #pragma unroll
    for (int o = 16; o > 0; o >>= 1) fq += __shfl_xor_sync(0xffffffffu, fq, o);
    float fd = sqrtf(fq);

    // neighbor point mean (lane k < 16 handles its own neighbor's coords)
    float px = 0.f, py = 0.f, pz = 0.f;
    if (l < KN && vflag) {
        px = pts[(size_t)sidx * 3 + 0];
        py = pts[(size_t)sidx * 3 + 1];
        pz = pts[(size_t)sidx * 3 + 2];
    }
    #pragma unroll
    for (int o = 16; o > 0; o >>= 1) {
        px += __shfl_xor_sync(0xffffffffu, px, o);
        py += __shfl_xor_sync(0xffffffffu, py, o);
        pz += __shfl_xor_sync(0xffffffffu, pz, o);
    }
    float cx = pts[(size_t)n * 3 + 0] - px * inv;
    float cy = pts[(size_t)n * 3 + 1] - py * inv;
    float cz = pts[(size_t)n * 3 + 2] - pz * inv;
    float cd = sqrtf(cx * cx + cy * cy + cz * cz);

    // boundary MLP (2 -> 128 -> 1), lane covers hidden units l, l+32, l+64, l+96
    float acc = 0.f;
    #pragma unroll
    for (int j = 0; j < 4; j++) {
        int u = l + j * 32;
        float h = gelu_fast(fd * bw1[u] + cd * bw1[CH + u] + bb1[u]);
        acc += h * bw2[u];
    }
    #pragma unroll
    for (int o = 16; o > 0; o >>= 1) acc += __shfl_xor_sync(0xffffffffu, acc, o);
    if (l == 0) g_bnd[n] = sigm(acc + bb2[0]);
}

// ---------------- mma helpers ------------------------------------------------
__device__ __forceinline__ void mma16816(float (&c)[4], const uint32_t (&a)[4],
                                         uint32_t b0, uint32_t b1) {
    asm volatile(
        "mma.sync.aligned.m16n8k16.row.col.f32.bf16.bf16.f32 "
        "{%0,%1,%2,%3}, {%4,%5,%6,%7}, {%8,%9}, {%0,%1,%2,%3};\n"
        : "+f"(c[0]), "+f"(c[1]), "+f"(c[2]), "+f"(c[3])
        : "r"(a[0]), "r"(a[1]), "r"(a[2]), "r"(a[3]), "r"(b0), "r"(b1));
}

__device__ __forceinline__ void ldm4(uint32_t (&r)[4], uint32_t addr) {
    asm volatile("ldmatrix.sync.aligned.m8n8.x4.shared.b16 {%0,%1,%2,%3}, [%4];"
                 : "=r"(r[0]), "=r"(r[1]), "=r"(r[2]), "=r"(r[3]) : "r"(addr));
}

__device__ __forceinline__ void frag_init(float (&c)[4][2][4],
                                          const float* __restrict__ bias,
                                          const float* __restrict__ wb,
                                          const float* bndp,
                                          int warp, int g, int tig) {
    #pragma unroll
    for (int sub = 0; sub < 2; sub++) {
        int nA = warp * 16 + sub * 8 + tig * 2;
        float bA = bias[nA], bB = bias[nA + 1];
        float wA = wb ? wb[nA] : 0.f, wB = wb ? wb[nA + 1] : 0.f;
        #pragma unroll
        for (int mt = 0; mt < 4; mt++) {
            float e0 = bndp ? bndp[mt * 16 + g] : 0.f;
            float e8 = bndp ? bndp[mt * 16 + g + 8] : 0.f;
            c[mt][sub][0] = bA + e0 * wA;
            c[mt][sub][1] = bB + e0 * wB;
            c[mt][sub][2] = bA + e8 * wA;
            c[mt][sub][3] = bB + e8 * wB;
        }
    }
}

// A from smem via ldmatrix.x4; B from fragment-packed global (L2-hot)
__device__ __forceinline__ void gemm_acc(float (&c)[4][2][4], uint32_t abase,
                                         const uint2* __restrict__ pk,
                                         int warp, int lane) {
    int rsel = (lane & 7) + ((lane >> 3) & 1) * 8;
    int csel = (lane >> 4) * 8;
    uint32_t off0 = abase + (uint32_t)((rsel * ASTRIDE + csel) * 2);
    #pragma unroll
    for (int kk = 0; kk < 8; kk++) {
        uint32_t a[4][4];
        #pragma unroll
        for (int mt = 0; mt < 4; mt++)
            ldm4(a[mt], off0 + mt * (16 * ASTRIDE * 2) + kk * 32);
        #pragma unroll
        for (int sub = 0; sub < 2; sub++) {
            uint2 b = pk[((warp * 2 + sub) * 8 + kk) * 32 + lane];
            #pragma unroll
            for (int mt = 0; mt < 4; mt++)
                mma16816(c[mt][sub], a[mt], b.x, b.y);
        }
    }
}

__device__ __forceinline__ void frag_store(__nv_bfloat16 (*D)[ASTRIDE],
                                           const float (&c)[4][2][4], int act,
                                           int warp, int g, int tig) {
    #pragma unroll
    for (int sub = 0; sub < 2; sub++) {
        int nA = warp * 16 + sub * 8 + tig * 2;
        #pragma unroll
        for (int mt = 0; mt < 4; mt++) {
            int r = mt * 16 + g;
            float v0 = c[mt][sub][0], v1 = c[mt][sub][1];
            float v2 = c[mt][sub][2], v3 = c[mt][sub][3];
            if (act) { v0 = gelu_fast(v0); v1 = gelu_fast(v1);
                       v2 = gelu_fast(v2); v3 = gelu_fast(v3); }
            __nv_bfloat162 p01, p23;
            p01.x = __float2bfloat16(v0); p01.y = __float2bfloat16(v1);
            p23.x = __float2bfloat16(v2); p23.y = __float2bfloat16(v3);
            *reinterpret_cast<uint32_t*>(&D[r][nA])     = *reinterpret_cast<uint32_t*>(&p01);
            *reinterpret_cast<uint32_t*>(&D[r + 8][nA]) = *reinterpret_cast<uint32_t*>(&p23);
        }
    }
}

// ---------------- K_mlp: fused MLPs, BP=64, single accumulator set ----------
#define SMEM_ARR (BP * ASTRIDE * 2)          // 17408
#define SMEM_MLP (4 * SMEM_ARR + 256 + 768)  // xs,ms,cs,hs + bnd + cpt = 70656

__global__ __launch_bounds__(256, 2)
void k_mlp(const float* __restrict__ pts, const float* __restrict__ feats,
           const float* __restrict__ cpw1, const float* __restrict__ cpb1,
           const float* __restrict__ cpb2,
           const float* __restrict__ mw1,  const float* __restrict__ mb1,
           const float* __restrict__ mb2,
           const float* __restrict__ gw1,  const float* __restrict__ gb1,
           const float* __restrict__ gb2,
           const float* __restrict__ ob,
           float* __restrict__ out) {
    extern __shared__ char dyn[];
    __nv_bfloat16 (*xs)[ASTRIDE] = reinterpret_cast<__nv_bfloat16(*)[ASTRIDE]>(dyn);
    __nv_bfloat16 (*ms)[ASTRIDE] = reinterpret_cast<__nv_bfloat16(*)[ASTRIDE]>(dyn + SMEM_ARR);
    __nv_bfloat16 (*cs)[ASTRIDE] = reinterpret_cast<__nv_bfloat16(*)[ASTRIDE]>(dyn + 2 * SMEM_ARR);
    __nv_bfloat16 (*hs)[ASTRIDE] = reinterpret_cast<__nv_bfloat16(*)[ASTRIDE]>(dyn + 3 * SMEM_ARR);
    float* bnd       = reinterpret_cast<float*>(dyn + 4 * SMEM_ARR);
    float (*cpt)[3]  = reinterpret_cast<float(*)[3]>(dyn + 4 * SMEM_ARR + 256);
    __shared__ float sh2[8][9];
    __shared__ float s_mean[3], s_scl[3];

    int t = threadIdx.x;
    int lane = t & 31, warp = t >> 5, g = lane >> 2, tig = lane & 3;
    int p0 = blockIdx.x * BP;

    uint32_t a_xs = (uint32_t)__cvta_generic_to_shared(xs);
    uint32_t a_ms = (uint32_t)__cvta_generic_to_shared(ms);
    uint32_t a_cs = (uint32_t)__cvta_generic_to_shared(cs);
    uint32_t a_hs = (uint32_t)__cvta_generic_to_shared(hs);

    // load x / mf tiles as bf16x2 words (pad rows are zero-initialized globals)
    {
        const uint32_t* xb32 = reinterpret_cast<const uint32_t*>(g_xb);
        const uint32_t* mb32 = reinterpret_cast<const uint32_t*>(g_mfb);
        int pair = t & 63, pr0 = t >> 6;
        #pragma unroll
        for (int p = pr0; p < BP; p += 4) {
            uint32_t vx = xb32[(size_t)(p0 + p) * 64 + pair];
            uint32_t vm = mb32[(size_t)(p0 + p) * 64 + pair];
            *reinterpret_cast<uint32_t*>(&xs[p][pair * 2]) = vx;
            *reinterpret_cast<uint32_t*>(&ms[p][pair * 2]) = vm;
        }
    }
    if (t < BP) bnd[t] = g_bnd[p0 + t];

    // combine point-stat partials (replaces separate psum2 kernel; L2-hot)
    {
        float r[9];
        #pragma unroll
        for (int j = 0; j < 9; j++) r[j] = g_part[t * 9 + j];
        #pragma unroll
        for (int o = 16; o > 0; o >>= 1) {
            r[0] += __shfl_xor_sync(0xffffffffu, r[0], o);
            r[1] += __shfl_xor_sync(0xffffffffu, r[1], o);
            r[2] += __shfl_xor_sync(0xffffffffu, r[2], o);
            r[3] = fminf(r[3], __shfl_xor_sync(0xffffffffu, r[3], o));
            r[4] = fminf(r[4], __shfl_xor_sync(0xffffffffu, r[4], o));
            r[5] = fminf(r[5], __shfl_xor_sync(0xffffffffu, r[5], o));
            r[6] = fmaxf(r[6], __shfl_xor_sync(0xffffffffu, r[6], o));
            r[7] = fmaxf(r[7], __shfl_xor_sync(0xffffffffu, r[7], o));
            r[8] = fmaxf(r[8], __shfl_xor_sync(0xffffffffu, r[8], o));
        }
        if (lane == 0)
            #pragma unroll
            for (int j = 0; j < 9; j++) sh2[warp][j] = r[j];
        __syncthreads();
        if (t == 0) {
            #pragma unroll
            for (int j = 0; j < 9; j++) r[j] = sh2[0][j];
            #pragma unroll
            for (int i = 1; i < 8; i++) {
                r[0] += sh2[i][0]; r[1] += sh2[i][1]; r[2] += sh2[i][2];
                r[3] = fminf(r[3], sh2[i][3]); r[4] = fminf(r[4], sh2[i][4]);
                r[5] = fminf(r[5], sh2[i][5]);
                r[6] = fmaxf(r[6], sh2[i][6]); r[7] = fmaxf(r[7], sh2[i][7]);
                r[8] = fmaxf(r[8], sh2[i][8]);
            }
            #pragma unroll
            for (int d = 0; d < 3; d++) {
                float mean = r[d] * (1.0f / NPTS);
                s_mean[d] = mean;
                s_scl[d]  = fmaxf(fmaxf(r[6 + d] - mean, mean - r[3 + d]), 1e-6f);
            }
        }
        __syncthreads();
    }

    if (t < BP * 3) {
        int p = t / 3, d = t - 3 * p;
        int row = min(p0 + p, NPTS - 1);
        cpt[p][d] = (pts[(size_t)row * 3 + d] - s_mean[d]) / s_scl[d];
    }
    __syncthreads();

    // coord-embed hidden (3 -> 128), SIMT
    {
        int col = t & 127, half = t >> 7;
        float w0 = cpw1[col], w1 = cpw1[CH + col], w2 = cpw1[2 * CH + col], b = cpb1[col];
        #pragma unroll
        for (int p = half; p < BP; p += 2)
            hs[p][col] = __float2bfloat16(
                gelu_fast(cpt[p][0] * w0 + cpt[p][1] * w1 + cpt[p][2] * w2 + b));
    }
    __syncthreads();

    float c[4][2][4];

    // 1) coord_embed = coord_hidden @ cp_w2 + cp_b2  -> cs
    frag_init(c, cpb2, nullptr, nullptr, warp, g, tig);
    gemm_acc(c, a_hs, g_pk + 0 * 4096, warp, lane);
    frag_store(cs, c, 0, warp, g, tig);
    __syncthreads();

    // 2) mix hidden: [x | mf | bnd | ce] @ mix_w1 + b -> gelu -> hs
    frag_init(c, mb1, mw1 + 256 * CH, bnd, warp, g, tig);
    gemm_acc(c, a_xs, g_pk + 1 * 4096, warp, lane);
    gemm_acc(c, a_ms, g_pk + 2 * 4096, warp, lane);
    gemm_acc(c, a_cs, g_pk + 3 * 4096, warp, lane);
    __syncthreads();                 // everyone done reading hs (pass 1) + cs
    frag_store(hs, c, 1, warp, g, tig);

    // 3) gate hidden: [x | mf | bnd] @ gate_w1 + b -> gelu -> cs (ce dead)
    frag_init(c, gb1, gw1 + 256 * CH, bnd, warp, g, tig);
    gemm_acc(c, a_xs, g_pk + 5 * 4096, warp, lane);
    gemm_acc(c, a_ms, g_pk + 6 * 4096, warp, lane);
    __syncthreads();                 // cs reads (pass 2) done; hs stores visible
    frag_store(cs, c, 1, warp, g, tig);
    __syncthreads();

    // 4) gate = sigmoid(gate_hidden @ gate_w2 + b), packed to bf16x2 regs
    frag_init(c, gb2, nullptr, nullptr, warp, g, tig);
    gemm_acc(c, a_cs, g_pk + 7 * 4096, warp, lane);
    uint32_t ga[4][2][2];
    #pragma unroll
    for (int mt = 0; mt < 4; mt++)
        #pragma unroll
        for (int sub = 0; sub < 2; sub++) {
            __nv_bfloat162 p01, p23;
            p01.x = __float2bfloat16(sigm(c[mt][sub][0]));
            p01.y = __float2bfloat16(sigm(c[mt][sub][1]));
            p23.x = __float2bfloat16(sigm(c[mt][sub][2]));
            p23.y = __float2bfloat16(sigm(c[mt][sub][3]));
            ga[mt][sub][0] = *reinterpret_cast<uint32_t*>(&p01);
            ga[mt][sub][1] = *reinterpret_cast<uint32_t*>(&p23);
        }

    // 5) refined = mix_hidden @ mix_w2 + b;  rs = gate * refined -> xs (dead)
    frag_init(c, mb2, nullptr, nullptr, warp, g, tig);
    gemm_acc(c, a_hs, g_pk + 4 * 4096, warp, lane);
    #pragma unroll
    for (int mt = 0; mt < 4; mt++)
        #pragma unroll
        for (int sub = 0; sub < 2; sub++) {
            __nv_bfloat162 g01 = *reinterpret_cast<__nv_bfloat162*>(&ga[mt][sub][0]);
            __nv_bfloat162 g23 = *reinterpret_cast<__nv_bfloat162*>(&ga[mt][sub][1]);
            c[mt][sub][0] *= __bfloat162float(g01.x);
            c[mt][sub][1] *= __bfloat162float(g01.y);
            c[mt][sub][2] *= __bfloat162float(g23.x);
            c[mt][sub][3] *= __bfloat162float(g23.y);
        }
    __syncthreads();                 // xs reads (pass 3) done
    frag_store(xs, c, 0, warp, g, tig);
    __syncthreads();

    // 6) out = feats + rs @ out_w + out_b
    frag_init(c, ob, nullptr, nullptr, warp, g, tig);
    gemm_acc(c, a_xs, g_pk + 8 * 4096, warp, lane);
    #pragma unroll
    for (int sub = 0; sub < 2; sub++) {
        int nA = warp * 16 + sub * 8 + tig * 2;
        #pragma unroll
        for (int mt = 0; mt < 4; mt++) {
            int r = mt * 16 + g;
            int row0 = p0 + r, row8 = row0 + 8;
            if (row0 < NPTS) {
                size_t o = (size_t)row0 * CH + nA;
                float2 f = *reinterpret_cast<const float2*>(feats + o);
                float2 v; v.x = f.x + c[mt][sub][0]; v.y = f.y + c[mt][sub][1];
                *reinterpret_cast<float2*>(out + o) = v;
            }
            if (row8 < NPTS) {
                size_t o = (size_t)row8 * CH + nA;
                float2 f = *reinterpret_cast<const float2*>(feats + o);
                float2 v; v.x = f.x + c[mt][sub][2]; v.y = f.y + c[mt][sub][3];
                *reinterpret_cast<float2*>(out + o) = v;
            }
        }
    }
}

// ---------------- launch -----------------------------------------------------
extern "C" void kernel_launch(void* const* d_in, const int* in_sizes, int n_in,
                              void* d_out, int out_size) {
    const float* feats = (const float*)d_in[0];
    const float* pts   = (const float*)d_in[1];
    const int*   nbr   = (const int*)d_in[2];     // int64 downcast to int32 by harness
    const float* ln_g  = (const float*)d_in[3];
    const float* ln_b  = (const float*)d_in[4];
    const float* cpw1  = (const float*)d_in[5];
    const float* cpb1  = (const float*)d_in[6];
    const float* cpw2  = (const float*)d_in[7];
    const float* cpb2  = (const float*)d_in[8];
    const float* bw1   = (const float*)d_in[9];
    const float* bb1   = (const float*)d_in[10];
    const float* bw2   = (const float*)d_in[11];
    const float* bb2   = (const float*)d_in[12];
    const float* mw1   = (const float*)d_in[13];
    const float* mb1   = (const float*)d_in[14];
    const float* mw2   = (const float*)d_in[15];
    const float* mb2   = (const float*)d_in[16];
    const float* gw1   = (const float*)d_in[17];
    const float* gb1   = (const float*)d_in[18];
    const float* gw2   = (const float*)d_in[19];
    const float* gb2   = (const float*)d_in[20];
    const float* ow    = (const float*)d_in[21];
    const float* ob    = (const float*)d_in[22];
    float* out = (float*)d_out;

    (void)in_sizes; (void)n_in; (void)out_size;

    cudaFuncSetAttribute(k_mlp, cudaFuncAttributeMaxDynamicSharedMemorySize, SMEM_MLP);

    // 4 launches; index 3 (ncu capture slot) = k_mlp
    k_prep<<<144 + NBLK_RED, 256>>>(pts,
                                    cpw2,
                                    mw1,                 // mix rows   0..127 (x)
                                    mw1 + 128 * CH,      // mix rows 128..255 (mf)
                                    mw1 + 257 * CH,      // mix rows 257..384 (ce)
                                    mw2,
                                    gw1,                 // gate rows  0..127 (x)
                                    gw1 + 128 * CH,      // gate rows 128..255 (mf)
                                    gw2,
                                    ow);                                 // 0
    k_ln<<<(NPTS + 7) / 8, 256>>>(feats, ln_g, ln_b);                    // 1
    k_gather<<<(NPTS + 7) / 8, 256>>>(pts, nbr, bw1, bb1, bw2, bb2);     // 2
    k_mlp<<<NPAD / BP, 256, SMEM_MLP>>>(pts, feats,
                                        cpw1, cpb1, cpb2,
                                        mw1, mb1, mb2,
                                        gw1, gb1, gb2,
                                        ob, out);                        // 3
}

// round 11
// speedup vs baseline: 1.0109x; 1.0109x over previous
#include <cuda_runtime.h>
#include <cuda_bf16.h>
#include <math.h>
#include <stdint.h>

#define NPTS 100000
#define NPAD 100032          // 64-aligned padding (device globals zero-init)
#define CH   128
#define KN   16
#define BP   64              // points per k_mlp block (four m16 tiles)
#define NBLK_RED 256
#define ASTRIDE 136          // bf16 elems per smem row (272B) -> conflict-free

// ---------------- scratch (device globals; no allocations allowed) ----------
__device__ __nv_bfloat16 g_xb [(size_t)NPAD * CH];  // LayerNorm output (bf16)
__device__ __nv_bfloat16 g_mfb[(size_t)NPAD * CH];  // neighbor mean feature (bf16)
__device__ float         g_bnd[NPAD];               // boundary score
__device__ float         g_part[NBLK_RED * 9];      // per-block {sum3,min3,max3}
__device__ uint2         g_pk[9 * 4096];            // fragment-packed bf16 weights

// ---------------- fast math --------------------------------------------------
__device__ __forceinline__ float tanh_fast(float x) {
    float y; asm("tanh.approx.f32 %0, %1;" : "=f"(y) : "f"(x)); return y;
}
__device__ __forceinline__ float gelu_fast(float v) {
    float t = v * fmaf(v * v, 0.0356774081f, 0.7978845608f);
    return 0.5f * v * (1.0f + tanh_fast(t));
}
__device__ __forceinline__ float sigm(float v) {
    return 1.0f / (1.0f + __expf(-v));
}

// ---------------- K_prep: weight pack (blocks 0..143) + point stats ---------
__global__ void k_prep(const float* __restrict__ pts,
                       const float* __restrict__ w0, const float* __restrict__ w1,
                       const float* __restrict__ w2, const float* __restrict__ w3,
                       const float* __restrict__ w4, const float* __restrict__ w5,
                       const float* __restrict__ w6, const float* __restrict__ w7,
                       const float* __restrict__ w8) {
    if (blockIdx.x < 144) {
        int by = blockIdx.x / 16, bx = blockIdx.x % 16;
        const float* W;
        switch (by) {
            case 0: W = w0; break;  case 1: W = w1; break;  case 2: W = w2; break;
            case 3: W = w3; break;  case 4: W = w4; break;  case 5: W = w5; break;
            case 6: W = w6; break;  case 7: W = w7; break;  default: W = w8; break;
        }
        int idx = bx * 256 + threadIdx.x;      // 0..4095
        int lane = idx & 31;
        int kk   = (idx >> 5) & 7;
        int ns   = idx >> 8;
        int g = lane >> 2, tig = lane & 3;
        int n  = ns * 8 + g;
        int k0 = kk * 16 + tig * 2;
        __nv_bfloat162 lo, hi;
        lo.x = __float2bfloat16(W[(size_t)k0 * CH + n]);
        lo.y = __float2bfloat16(W[(size_t)(k0 + 1) * CH + n]);
        hi.x = __float2bfloat16(W[(size_t)(k0 + 8) * CH + n]);
        hi.y = __float2bfloat16(W[(size_t)(k0 + 9) * CH + n]);
        uint2 v;
        v.x = *reinterpret_cast<uint32_t*>(&lo);
        v.y = *reinterpret_cast<uint32_t*>(&hi);
        g_pk[by * 4096 + idx] = v;
        return;
    }
    int bid = blockIdx.x - 144;   // 0..255
    float s0 = 0.f, s1 = 0.f, s2 = 0.f;
    float mn0 = 1e30f, mn1 = 1e30f, mn2 = 1e30f;
    float mx0 = -1e30f, mx1 = -1e30f, mx2 = -1e30f;
    for (int i = bid * 256 + threadIdx.x; i < NPTS; i += NBLK_RED * 256) {
        float p0 = pts[3 * i + 0], p1 = pts[3 * i + 1], p2 = pts[3 * i + 2];
        s0 += p0; s1 += p1; s2 += p2;
        mn0 = fminf(mn0, p0); mn1 = fminf(mn1, p1); mn2 = fminf(mn2, p2);
        mx0 = fmaxf(mx0, p0); mx1 = fmaxf(mx1, p1); mx2 = fmaxf(mx2, p2);
    }
    __shared__ float sh[8][9];
    #pragma unroll
    for (int o = 16; o > 0; o >>= 1) {
        s0 += __shfl_xor_sync(0xffffffffu, s0, o);
        s1 += __shfl_xor_sync(0xffffffffu, s1, o);
        s2 += __shfl_xor_sync(0xffffffffu, s2, o);
        mn0 = fminf(mn0, __shfl_xor_sync(0xffffffffu, mn0, o));
        mn1 = fminf(mn1, __shfl_xor_sync(0xffffffffu, mn1, o));
        mn2 = fminf(mn2, __shfl_xor_sync(0xffffffffu, mn2, o));
        mx0 = fmaxf(mx0, __shfl_xor_sync(0xffffffffu, mx0, o));
        mx1 = fmaxf(mx1, __shfl_xor_sync(0xffffffffu, mx1, o));
        mx2 = fmaxf(mx2, __shfl_xor_sync(0xffffffffu, mx2, o));
    }
    int w = threadIdx.x >> 5, l = threadIdx.x & 31;
    if (l == 0) {
        sh[w][0] = s0;  sh[w][1] = s1;  sh[w][2] = s2;
        sh[w][3] = mn0; sh[w][4] = mn1; sh[w][5] = mn2;
        sh[w][6] = mx0; sh[w][7] = mx1; sh[w][8] = mx2;
    }
    __syncthreads();
    if (threadIdx.x == 0) {
        float r[9];
        #pragma unroll
        for (int j = 0; j < 9; j++) r[j] = sh[0][j];
        #pragma unroll
        for (int i = 1; i < 8; i++) {
            r[0] += sh[i][0]; r[1] += sh[i][1]; r[2] += sh[i][2];
            r[3] = fminf(r[3], sh[i][3]); r[4] = fminf(r[4], sh[i][4]);
            r[5] = fminf(r[5], sh[i][5]);
            r[6] = fmaxf(r[6], sh[i][6]); r[7] = fmaxf(r[7], sh[i][7]);
            r[8] = fmaxf(r[8], sh[i][8]);
        }
        #pragma unroll
        for (int j = 0; j < 9; j++) g_part[bid * 9 + j] = r[j];
    }
}

// ---------------- K_ln: LayerNorm, warp per row ------------------------------
__global__ void k_ln(const float* __restrict__ feats,
                     const float* __restrict__ gg, const float* __restrict__ bb) {
    int row = blockIdx.x * 8 + (threadIdx.x >> 5);
    if (row >= NPTS) return;
    int l = threadIdx.x & 31;
    float4 v = reinterpret_cast<const float4*>(feats + (size_t)row * CH)[l];
    float s = v.x + v.y + v.z + v.w;
    #pragma unroll
    for (int o = 16; o > 0; o >>= 1) s += __shfl_xor_sync(0xffffffffu, s, o);
    float mean = s * (1.0f / CH);
    float dx = v.x - mean, dy = v.y - mean, dz = v.z - mean, dw = v.w - mean;
    float q = dx * dx + dy * dy + dz * dz + dw * dw;
    #pragma unroll
    for (int o = 16; o > 0; o >>= 1) q += __shfl_xor_sync(0xffffffffu, q, o);
    float rstd = rsqrtf(q * (1.0f / CH) + 1e-5f);
    float4 g4 = reinterpret_cast<const float4*>(gg)[l];
    float4 b4 = reinterpret_cast<const float4*>(bb)[l];
    __nv_bfloat162 lo, hi;
    lo.x = __float2bfloat16(dx * rstd * g4.x + b4.x);
    lo.y = __float2bfloat16(dy * rstd * g4.y + b4.y);
    hi.x = __float2bfloat16(dz * rstd * g4.z + b4.z);
    hi.y = __float2bfloat16(dw * rstd * g4.w + b4.w);
    uint2 u;
    u.x = *reinterpret_cast<uint32_t*>(&lo);
    u.y = *reinterpret_cast<uint32_t*>(&hi);
    reinterpret_cast<uint2*>(g_xb + (size_t)row * CH)[l] = u;
}

// ---------------- K_gather: warp per point, f32x2 packed accumulate ---------
__global__ __launch_bounds__(256)
void k_gather(const float* __restrict__ pts,
              const int* __restrict__ nbr,
              const float* __restrict__ bw1, const float* __restrict__ bb1,
              const float* __restrict__ bw2, const float* __restrict__ bb2) {
    int w = threadIdx.x >> 5, l = threadIdx.x & 31;
    int n = blockIdx.x * 8 + w;
    if (n >= NPTS) return;

    int sidx = 0, vflag = 0;
    if (l < KN) {
        int v = nbr[(size_t)n * KN + l];
        vflag = (v >= 0 && v < NPTS) ? 1 : 0;
        sidx = v < 0 ? 0 : (v >= NPTS ? (NPTS - 1) : v);
    }
    unsigned ball = __ballot_sync(0xffffffffu, vflag);
    float inv = 1.0f / fmaxf((float)__popc(ball), 1.0f);

    const uint2* xb = reinterpret_cast<const uint2*>(g_xb);
    unsigned long long acc01 = 0ull, acc23 = 0ull;
    #pragma unroll
    for (int k = 0; k < KN; k++) {
        int idx = __shfl_sync(0xffffffffu, sidx, k);
        float wk = ((ball >> k) & 1u) ? 1.0f : 0.0f;
        unsigned long long wk2;
        asm("mov.b64 %0, {%1,%1};" : "=l"(wk2) : "f"(wk));
        uint2 u = xb[(size_t)idx * 32 + l];
        uint32_t f0 = u.x << 16, f1 = u.x & 0xffff0000u;
        uint32_t f2 = u.y << 16, f3 = u.y & 0xffff0000u;
        unsigned long long v01, v23;
        asm("mov.b64 %0, {%1,%2};" : "=l"(v01) : "r"(f0), "r"(f1));
        asm("mov.b64 %0, {%1,%2};" : "=l"(v23) : "r"(f2), "r"(f3));
        asm("fma.rn.f32x2 %0, %1, %2, %0;" : "+l"(acc01) : "l"(v01), "l"(wk2));
        asm("fma.rn.f32x2 %0, %1, %2, %0;" : "+l"(acc23) : "l"(v23), "l"(wk2));
    }
    float a0, a1, a2, a3;
    asm("mov.b64 {%0,%1}, %2;" : "=f"(a0), "=f"(a1) : "l"(acc01));
    asm("mov.b64 {%0,%1}, %2;" : "=f"(a2), "=f"(a3) : "l"(acc23));
    float mf0 = a0 * inv, mf1 = a1 * inv, mf2 = a2 * inv, mf3 = a3 * inv;
    {
        __nv_bfloat162 p0, p1;
        p0.x = __float2bfloat16(mf0); p0.y = __float2bfloat16(mf1);
        p1.x = __float2bfloat16(mf2); p1.y = __float2bfloat16(mf3);
        uint2 u;
        u.x = *reinterpret_cast<uint32_t*>(&p0);
        u.y = *reinterpret_cast<uint32_t*>(&p1);
        reinterpret_cast<uint2*>(g_mfb)[(size_t)n * 32 + l] = u;
    }

    uint2 xu = xb[(size_t)n * 32 + l];
    float x0 = __uint_as_float(xu.x << 16);
    float x1 = __uint_as_float(xu.x & 0xffff0000u);
    float x2 = __uint_as_float(xu.y << 16);
    float x3 = __uint_as_float(xu.y & 0xffff0000u);
    float d0 = x0 - mf0, d1 = x1 - mf1, d2 = x2 - mf2, d3 = x3 - mf3;
    float fq = d0 * d0 + d1 * d1 + d2 * d2 + d3 * d3;
    #pragma unroll
    for (int o = 16; o > 0; o >>= 1) fq += __shfl_xor_sync(0xffffffffu, fq, o);
    float fd = sqrtf(fq);

    float px = 0.f, py = 0.f, pz = 0.f;
    if (l < KN && vflag) {
        px = pts[(size_t)sidx * 3 + 0];
        py = pts[(size_t)sidx * 3 + 1];
        pz = pts[(size_t)sidx * 3 + 2];
    }
    #pragma unroll
    for (int o = 16; o > 0; o >>= 1) {
        px += __shfl_xor_sync(0xffffffffu, px, o);
        py += __shfl_xor_sync(0xffffffffu, py, o);
        pz += __shfl_xor_sync(0xffffffffu, pz, o);
    }
    float cx = pts[(size_t)n * 3 + 0] - px * inv;
    float cy = pts[(size_t)n * 3 + 1] - py * inv;
    float cz = pts[(size_t)n * 3 + 2] - pz * inv;
    float cd = sqrtf(cx * cx + cy * cy + cz * cz);

    float acc = 0.f;
    #pragma unroll
    for (int j = 0; j < 4; j++) {
        int u = l + j * 32;
        float h = gelu_fast(fd * bw1[u] + cd * bw1[CH + u] + bb1[u]);
        acc += h * bw2[u];
    }
    #pragma unroll
    for (int o = 16; o > 0; o >>= 1) acc += __shfl_xor_sync(0xffffffffu, acc, o);
    if (l == 0) g_bnd[n] = sigm(acc + bb2[0]);
}

// ---------------- mma helpers (4 warps, 32 N-cols per warp) -----------------
__device__ __forceinline__ void mma16816(float (&c)[4], const uint32_t (&a)[4],
                                         uint32_t b0, uint32_t b1) {
    asm volatile(
        "mma.sync.aligned.m16n8k16.row.col.f32.bf16.bf16.f32 "
        "{%0,%1,%2,%3}, {%4,%5,%6,%7}, {%8,%9}, {%0,%1,%2,%3};\n"
        : "+f"(c[0]), "+f"(c[1]), "+f"(c[2]), "+f"(c[3])
        : "r"(a[0]), "r"(a[1]), "r"(a[2]), "r"(a[3]), "r"(b0), "r"(b1));
}

__device__ __forceinline__ void ldm4(uint32_t (&r)[4], uint32_t addr) {
    asm volatile("ldmatrix.sync.aligned.m8n8.x4.shared.b16 {%0,%1,%2,%3}, [%4];"
                 : "=r"(r[0]), "=r"(r[1]), "=r"(r[2]), "=r"(r[3]) : "r"(addr));
}

__device__ __forceinline__ void frag_init(float (&c)[4][4][4],
                                          const float* __restrict__ bias,
                                          const float* __restrict__ wb,
                                          const float* bndp,
                                          int warp, int g, int tig) {
    #pragma unroll
    for (int sub = 0; sub < 4; sub++) {
        int nA = warp * 32 + sub * 8 + tig * 2;
        float bA = bias[nA], bB = bias[nA + 1];
        float wA = wb ? wb[nA] : 0.f, wB = wb ? wb[nA + 1] : 0.f;
        #pragma unroll
        for (int mt = 0; mt < 4; mt++) {
            float e0 = bndp ? bndp[mt * 16 + g] : 0.f;
            float e8 = bndp ? bndp[mt * 16 + g + 8] : 0.f;
            c[mt][sub][0] = bA + e0 * wA;
            c[mt][sub][1] = bB + e0 * wB;
            c[mt][sub][2] = bA + e8 * wA;
            c[mt][sub][3] = bB + e8 * wB;
        }
    }
}

// A from smem via ldmatrix.x4 (4-warp: half the replication of 8-warp);
// B from fragment-packed global (L2-resident)
__device__ __forceinline__ void gemm_acc(float (&c)[4][4][4], uint32_t abase,
                                         const uint2* __restrict__ pk,
                                         int warp, int lane) {
    int rsel = (lane & 7) + ((lane >> 3) & 1) * 8;
    int csel = (lane >> 4) * 8;
    uint32_t off0 = abase + (uint32_t)((rsel * ASTRIDE + csel) * 2);
    #pragma unroll
    for (int kk = 0; kk < 8; kk++) {
        uint32_t a[4][4];
        #pragma unroll
        for (int mt = 0; mt < 4; mt++)
            ldm4(a[mt], off0 + mt * (16 * ASTRIDE * 2) + kk * 32);
        #pragma unroll
        for (int sub = 0; sub < 4; sub++) {
            uint2 b = pk[((warp * 4 + sub) * 8 + kk) * 32 + lane];
            #pragma unroll
            for (int mt = 0; mt < 4; mt++)
                mma16816(c[mt][sub], a[mt], b.x, b.y);
        }
    }
}

__device__ __forceinline__ void frag_store(__nv_bfloat16 (*D)[ASTRIDE],
                                           const float (&c)[4][4][4], int act,
                                           int warp, int g, int tig) {
    #pragma unroll
    for (int sub = 0; sub < 4; sub++) {
        int nA = warp * 32 + sub * 8 + tig * 2;
        #pragma unroll
        for (int mt = 0; mt < 4; mt++) {
            int r = mt * 16 + g;
            float v0 = c[mt][sub][0], v1 = c[mt][sub][1];
            float v2 = c[mt][sub][2], v3 = c[mt][sub][3];
            if (act) { v0 = gelu_fast(v0); v1 = gelu_fast(v1);
                       v2 = gelu_fast(v2); v3 = gelu_fast(v3); }
            __nv_bfloat162 p01, p23;
            p01.x = __float2bfloat16(v0); p01.y = __float2bfloat16(v1);
            p23.x = __float2bfloat16(v2); p23.y = __float2bfloat16(v3);
            *reinterpret_cast<uint32_t*>(&D[r][nA])     = *reinterpret_cast<uint32_t*>(&p01);
            *reinterpret_cast<uint32_t*>(&D[r + 8][nA]) = *reinterpret_cast<uint32_t*>(&p23);
        }
    }
}

// ---------------- K_mlp: fused MLPs, BP=64, 128 thr, 3 CTA/SM ---------------
#define SMEM_ARR (BP * ASTRIDE * 2)          // 17408
#define SMEM_MLP (4 * SMEM_ARR + 256 + 768)  // xs,ms,cs,hs + bnd + cpt = 70656

__global__ __launch_bounds__(128, 3)
void k_mlp(const float* __restrict__ pts, const float* __restrict__ feats,
           const float* __restrict__ cpw1, const float* __restrict__ cpb1,
           const float* __restrict__ cpb2,
           const float* __restrict__ mw1,  const float* __restrict__ mb1,
           const float* __restrict__ mb2,
           const float* __restrict__ gw1,  const float* __restrict__ gb1,
           const float* __restrict__ gb2,
           const float* __restrict__ ob,
           float* __restrict__ out) {
    extern __shared__ char dyn[];
    __nv_bfloat16 (*xs)[ASTRIDE] = reinterpret_cast<__nv_bfloat16(*)[ASTRIDE]>(dyn);
    __nv_bfloat16 (*ms)[ASTRIDE] = reinterpret_cast<__nv_bfloat16(*)[ASTRIDE]>(dyn + SMEM_ARR);
    __nv_bfloat16 (*cs)[ASTRIDE] = reinterpret_cast<__nv_bfloat16(*)[ASTRIDE]>(dyn + 2 * SMEM_ARR);
    __nv_bfloat16 (*hs)[ASTRIDE] = reinterpret_cast<__nv_bfloat16(*)[ASTRIDE]>(dyn + 3 * SMEM_ARR);
    float* bnd       = reinterpret_cast<float*>(dyn + 4 * SMEM_ARR);
    float (*cpt)[3]  = reinterpret_cast<float(*)[3]>(dyn + 4 * SMEM_ARR + 256);
    __shared__ float sh2[4][9];
    __shared__ float s_mean[3], s_scl[3];

    int t = threadIdx.x;                 // 128 threads
    int lane = t & 31, warp = t >> 5, g = lane >> 2, tig = lane & 3;
    int p0 = blockIdx.x * BP;

    uint32_t a_xs = (uint32_t)__cvta_generic_to_shared(xs);
    uint32_t a_ms = (uint32_t)__cvta_generic_to_shared(ms);
    uint32_t a_cs = (uint32_t)__cvta_generic_to_shared(cs);
    uint32_t a_hs = (uint32_t)__cvta_generic_to_shared(hs);

    // load x / mf tiles as bf16x2 words
    {
        const uint32_t* xb32 = reinterpret_cast<const uint32_t*>(g_xb);
        const uint32_t* mb32 = reinterpret_cast<const uint32_t*>(g_mfb);
        int pair = t & 63, pr0 = t >> 6;   // 2 row-groups of 64 pairs
        #pragma unroll
        for (int p = pr0; p < BP; p += 2) {
            uint32_t vx = xb32[(size_t)(p0 + p) * 64 + pair];
            uint32_t vm = mb32[(size_t)(p0 + p) * 64 + pair];
            *reinterpret_cast<uint32_t*>(&xs[p][pair * 2]) = vx;
            *reinterpret_cast<uint32_t*>(&ms[p][pair * 2]) = vm;
        }
    }
    if (t < BP) bnd[t] = g_bnd[p0 + t];

    // combine point-stat partials (256 partials, 128 threads: 2 each)
    {
        float r[9], q[9];
        #pragma unroll
        for (int j = 0; j < 9; j++) {
            r[j] = g_part[t * 9 + j];
            q[j] = g_part[(t + 128) * 9 + j];
        }
        r[0] += q[0]; r[1] += q[1]; r[2] += q[2];
        r[3] = fminf(r[3], q[3]); r[4] = fminf(r[4], q[4]); r[5] = fminf(r[5], q[5]);
        r[6] = fmaxf(r[6], q[6]); r[7] = fmaxf(r[7], q[7]); r[8] = fmaxf(r[8], q[8]);
        #pragma unroll
        for (int o = 16; o > 0; o >>= 1) {
            r[0] += __shfl_xor_sync(0xffffffffu, r[0], o);
            r[1] += __shfl_xor_sync(0xffffffffu, r[1], o);
            r[2] += __shfl_xor_sync(0xffffffffu, r[2], o);
            r[3] = fminf(r[3], __shfl_xor_sync(0xffffffffu, r[3], o));
            r[4] = fminf(r[4], __shfl_xor_sync(0xffffffffu, r[4], o));
            r[5] = fminf(r[5], __shfl_xor_sync(0xffffffffu, r[5], o));
            r[6] = fmaxf(r[6], __shfl_xor_sync(0xffffffffu, r[6], o));
            r[7] = fmaxf(r[7], __shfl_xor_sync(0xffffffffu, r[7], o));
            r[8] = fmaxf(r[8], __shfl_xor_sync(0xffffffffu, r[8], o));
        }
        if (lane == 0)
            #pragma unroll
            for (int j = 0; j < 9; j++) sh2[warp][j] = r[j];
        __syncthreads();
        if (t == 0) {
            #pragma unroll
            for (int j = 0; j < 9; j++) r[j] = sh2[0][j];
            #pragma unroll
            for (int i = 1; i < 4; i++) {
                r[0] += sh2[i][0]; r[1] += sh2[i][1]; r[2] += sh2[i][2];
                r[3] = fminf(r[3], sh2[i][3]); r[4] = fminf(r[4], sh2[i][4]);
                r[5] = fminf(r[5], sh2[i][5]);
                r[6] = fmaxf(r[6], sh2[i][6]); r[7] = fmaxf(r[7], sh2[i][7]);
                r[8] = fmaxf(r[8], sh2[i][8]);
            }
            #pragma unroll
            for (int d = 0; d < 3; d++) {
                float mean = r[d] * (1.0f / NPTS);
                s_mean[d] = mean;
                s_scl[d]  = fmaxf(fmaxf(r[6 + d] - mean, mean - r[3 + d]), 1e-6f);
            }
        }
        __syncthreads();
    }

    for (int e = t; e < BP * 3; e += 128) {
        int p = e / 3, d = e - 3 * p;
        int row = min(p0 + p, NPTS - 1);
        cpt[p][d] = (pts[(size_t)row * 3 + d] - s_mean[d]) / s_scl[d];
    }
    __syncthreads();

    // coord-embed hidden (3 -> 128), SIMT: thread t owns column t
    {
        float w0 = cpw1[t], w1 = cpw1[CH + t], w2 = cpw1[2 * CH + t], b = cpb1[t];
        #pragma unroll 4
        for (int p = 0; p < BP; p++)
            hs[p][t] = __float2bfloat16(
                gelu_fast(cpt[p][0] * w0 + cpt[p][1] * w1 + cpt[p][2] * w2 + b));
    }
    __syncthreads();

    float c[4][4][4];

    // 1) coord_embed = coord_hidden @ cp_w2 + cp_b2  -> cs
    frag_init(c, cpb2, nullptr, nullptr, warp, g, tig);
    gemm_acc(c, a_hs, g_pk + 0 * 4096, warp, lane);
    frag_store(cs, c, 0, warp, g, tig);
    __syncthreads();

    // 2) mix hidden: [x | mf | bnd | ce] @ mix_w1 + b -> gelu -> hs
    frag_init(c, mb1, mw1 + 256 * CH, bnd, warp, g, tig);
    gemm_acc(c, a_xs, g_pk + 1 * 4096, warp, lane);
    gemm_acc(c, a_ms, g_pk + 2 * 4096, warp, lane);
    gemm_acc(c, a_cs, g_pk + 3 * 4096, warp, lane);
    __syncthreads();                 // everyone done reading hs (pass 1) + cs
    frag_store(hs, c, 1, warp, g, tig);

    // 3) gate hidden: [x | mf | bnd] @ gate_w1 + b -> gelu -> cs (ce dead)
    frag_init(c, gb1, gw1 + 256 * CH, bnd, warp, g, tig);
    gemm_acc(c, a_xs, g_pk + 5 * 4096, warp, lane);
    gemm_acc(c, a_ms, g_pk + 6 * 4096, warp, lane);
    __syncthreads();                 // cs reads (pass 2) done; hs stores visible
    frag_store(cs, c, 1, warp, g, tig);
    __syncthreads();

    // 4) gate = sigmoid(gate_hidden @ gate_w2 + b), packed to bf16x2 regs
    frag_init(c, gb2, nullptr, nullptr, warp, g, tig);
    gemm_acc(c, a_cs, g_pk + 7 * 4096, warp, lane);
    uint32_t ga[4][4][2];
    #pragma unroll
    for (int mt = 0; mt < 4; mt++)
        #pragma unroll
        for (int sub = 0; sub < 4; sub++) {
            __nv_bfloat162 p01, p23;
            p01.x = __float2bfloat16(sigm(c[mt][sub][0]));
            p01.y = __float2bfloat16(sigm(c[mt][sub][1]));
            p23.x = __float2bfloat16(sigm(c[mt][sub][2]));
            p23.y = __float2bfloat16(sigm(c[mt][sub][3]));
            ga[mt][sub][0] = *reinterpret_cast<uint32_t*>(&p01);
            ga[mt][sub][1] = *reinterpret_cast<uint32_t*>(&p23);
        }

    // 5) refined = mix_hidden @ mix_w2 + b;  rs = gate * refined -> xs (dead)
    frag_init(c, mb2, nullptr, nullptr, warp, g, tig);
    gemm_acc(c, a_hs, g_pk + 4 * 4096, warp, lane);
    #pragma unroll
    for (int mt = 0; mt < 4; mt++)
        #pragma unroll
        for (int sub = 0; sub < 4; sub++) {
            __nv_bfloat162 g01 = *reinterpret_cast<__nv_bfloat162*>(&ga[mt][sub][0]);
            __nv_bfloat162 g23 = *reinterpret_cast<__nv_bfloat162*>(&ga[mt][sub][1]);
            c[mt][sub][0] *= __bfloat162float(g01.x);
            c[mt][sub][1] *= __bfloat162float(g01.y);
            c[mt][sub][2] *= __bfloat162float(g23.x);
            c[mt][sub][3] *= __bfloat162float(g23.y);
        }
    __syncthreads();                 // xs reads (pass 3) done
    frag_store(xs, c, 0, warp, g, tig);
    __syncthreads();

    // 6) out = feats + rs @ out_w + out_b
    frag_init(c, ob, nullptr, nullptr, warp, g, tig);
    gemm_acc(c, a_xs, g_pk + 8 * 4096, warp, lane);
    #pragma unroll
    for (int sub = 0; sub < 4; sub++) {
        int nA = warp * 32 + sub * 8 + tig * 2;
        #pragma unroll
        for (int mt = 0; mt < 4; mt++) {
            int r = mt * 16 + g;
            int row0 = p0 + r, row8 = row0 + 8;
            if (row0 < NPTS) {
                size_t o = (size_t)row0 * CH + nA;
                float2 f = *reinterpret_cast<const float2*>(feats + o);
                float2 v; v.x = f.x + c[mt][sub][0]; v.y = f.y + c[mt][sub][1];
                *reinterpret_cast<float2*>(out + o) = v;
            }
            if (row8 < NPTS) {
                size_t o = (size_t)row8 * CH + nA;
                float2 f = *reinterpret_cast<const float2*>(feats + o);
                float2 v; v.x = f.x + c[mt][sub][2]; v.y = f.y + c[mt][sub][3];
                *reinterpret_cast<float2*>(out + o) = v;
            }
        }
    }
}

// ---------------- launch -----------------------------------------------------
extern "C" void kernel_launch(void* const* d_in, const int* in_sizes, int n_in,
                              void* d_out, int out_size) {
    const float* feats = (const float*)d_in[0];
    const float* pts   = (const float*)d_in[1];
    const int*   nbr   = (const int*)d_in[2];     // int64 downcast to int32 by harness
    const float* ln_g  = (const float*)d_in[3];
    const float* ln_b  = (const float*)d_in[4];
    const float* cpw1  = (const float*)d_in[5];
    const float* cpb1  = (const float*)d_in[6];
    const float* cpw2  = (const float*)d_in[7];
    const float* cpb2  = (const float*)d_in[8];
    const float* bw1   = (const float*)d_in[9];
    const float* bb1   = (const float*)d_in[10];
    const float* bw2   = (const float*)d_in[11];
    const float* bb2   = (const float*)d_in[12];
    const float* mw1   = (const float*)d_in[13];
    const float* mb1   = (const float*)d_in[14];
    const float* mw2   = (const float*)d_in[15];
    const float* mb2   = (const float*)d_in[16];
    const float* gw1   = (const float*)d_in[17];
    const float* gb1   = (const float*)d_in[18];
    const float* gw2   = (const float*)d_in[19];
    const float* gb2   = (const float*)d_in[20];
    const float* ow    = (const float*)d_in[21];
    const float* ob    = (const float*)d_in[22];
    float* out = (float*)d_out;

    (void)in_sizes; (void)n_in; (void)out_size;

    cudaFuncSetAttribute(k_mlp, cudaFuncAttributeMaxDynamicSharedMemorySize, SMEM_MLP);

    // 4 launches; index 3 (ncu capture slot) = k_mlp
    k_prep<<<144 + NBLK_RED, 256>>>(pts,
                                    cpw2,
                                    mw1,                 // mix rows   0..127 (x)
                                    mw1 + 128 * CH,      // mix rows 128..255 (mf)
                                    mw1 + 257 * CH,      // mix rows 257..384 (ce)
                                    mw2,
                                    gw1,                 // gate rows  0..127 (x)
                                    gw1 + 128 * CH,      // gate rows 128..255 (mf)
                                    gw2,
                                    ow);                                 // 0
    k_ln<<<(NPTS + 7) / 8, 256>>>(feats, ln_g, ln_b);                    // 1
    k_gather<<<(NPTS + 7) / 8, 256>>>(pts, nbr, bw1, bb1, bw2, bb2);     // 2
    k_mlp<<<NPAD / BP, 128, SMEM_MLP>>>(pts, feats,
                                        cpw1, cpb1, cpb2,
                                        mw1, mb1, mb2,
                                        gw1, gb1, gb2,
                                        ob, out);                        // 3
}

// round 12
// speedup vs baseline: 1.1129x; 1.1009x over previous
#include <cuda_runtime.h>
#include <cuda_bf16.h>
#include <math.h>
#include <stdint.h>

#define NPTS 100000
#define NPAD 100032          // 32-aligned padding (device globals zero-init)
#define CH   128
#define KN   16
#define BP   32              // points per k_mlp block (two m16 tiles)
#define NBLK_RED 256
#define ASTRIDE 136          // bf16 elems per smem row (272B) -> conflict-free

// ---------------- scratch (device globals; no allocations allowed) ----------
__device__ __nv_bfloat16 g_xb [(size_t)NPAD * CH];  // LayerNorm output (bf16)
__device__ __nv_bfloat16 g_mfb[(size_t)NPAD * CH];  // neighbor mean feature (bf16)
__device__ float         g_bnd[NPAD];               // boundary score
__device__ float         g_part[NBLK_RED * 9];      // per-block {sum3,min3,max3}
__device__ uint2         g_pk[9 * 4096];            // fragment-packed bf16 weights

// ---------------- fast math --------------------------------------------------
__device__ __forceinline__ float tanh_fast(float x) {
    float y; asm("tanh.approx.f32 %0, %1;" : "=f"(y) : "f"(x)); return y;
}
__device__ __forceinline__ float gelu_fast(float v) {
    float t = v * fmaf(v * v, 0.0356774081f, 0.7978845608f);
    return 0.5f * v * (1.0f + tanh_fast(t));
}
__device__ __forceinline__ float sigm(float v) {
    return 1.0f / (1.0f + __expf(-v));
}

// ---------------- K_prep: weight pack (blocks 0..143) + point stats ---------
__global__ void k_prep(const float* __restrict__ pts,
                       const float* __restrict__ w0, const float* __restrict__ w1,
                       const float* __restrict__ w2, const float* __restrict__ w3,
                       const float* __restrict__ w4, const float* __restrict__ w5,
                       const float* __restrict__ w6, const float* __restrict__ w7,
                       const float* __restrict__ w8) {
    if (blockIdx.x < 144) {
        int by = blockIdx.x / 16, bx = blockIdx.x % 16;
        const float* W;
        switch (by) {
            case 0: W = w0; break;  case 1: W = w1; break;  case 2: W = w2; break;
            case 3: W = w3; break;  case 4: W = w4; break;  case 5: W = w5; break;
            case 6: W = w6; break;  case 7: W = w7; break;  default: W = w8; break;
        }
        int idx = bx * 256 + threadIdx.x;      // 0..4095
        int lane = idx & 31;
        int kk   = (idx >> 5) & 7;
        int ns   = idx >> 8;
        int g = lane >> 2, tig = lane & 3;
        int n  = ns * 8 + g;
        int k0 = kk * 16 + tig * 2;
        __nv_bfloat162 lo, hi;
        lo.x = __float2bfloat16(W[(size_t)k0 * CH + n]);
        lo.y = __float2bfloat16(W[(size_t)(k0 + 1) * CH + n]);
        hi.x = __float2bfloat16(W[(size_t)(k0 + 8) * CH + n]);
        hi.y = __float2bfloat16(W[(size_t)(k0 + 9) * CH + n]);
        uint2 v;
        v.x = *reinterpret_cast<uint32_t*>(&lo);
        v.y = *reinterpret_cast<uint32_t*>(&hi);
        g_pk[by * 4096 + idx] = v;
        return;
    }
    int bid = blockIdx.x - 144;   // 0..255
    float s0 = 0.f, s1 = 0.f, s2 = 0.f;
    float mn0 = 1e30f, mn1 = 1e30f, mn2 = 1e30f;
    float mx0 = -1e30f, mx1 = -1e30f, mx2 = -1e30f;
    for (int i = bid * 256 + threadIdx.x; i < NPTS; i += NBLK_RED * 256) {
        float p0 = pts[3 * i + 0], p1 = pts[3 * i + 1], p2 = pts[3 * i + 2];
        s0 += p0; s1 += p1; s2 += p2;
        mn0 = fminf(mn0, p0); mn1 = fminf(mn1, p1); mn2 = fminf(mn2, p2);
        mx0 = fmaxf(mx0, p0); mx1 = fmaxf(mx1, p1); mx2 = fmaxf(mx2, p2);
    }
    __shared__ float sh[8][9];
    #pragma unroll
    for (int o = 16; o > 0; o >>= 1) {
        s0 += __shfl_xor_sync(0xffffffffu, s0, o);
        s1 += __shfl_xor_sync(0xffffffffu, s1, o);
        s2 += __shfl_xor_sync(0xffffffffu, s2, o);
        mn0 = fminf(mn0, __shfl_xor_sync(0xffffffffu, mn0, o));
        mn1 = fminf(mn1, __shfl_xor_sync(0xffffffffu, mn1, o));
        mn2 = fminf(mn2, __shfl_xor_sync(0xffffffffu, mn2, o));
        mx0 = fmaxf(mx0, __shfl_xor_sync(0xffffffffu, mx0, o));
        mx1 = fmaxf(mx1, __shfl_xor_sync(0xffffffffu, mx1, o));
        mx2 = fmaxf(mx2, __shfl_xor_sync(0xffffffffu, mx2, o));
    }
    int w = threadIdx.x >> 5, l = threadIdx.x & 31;
    if (l == 0) {
        sh[w][0] = s0;  sh[w][1] = s1;  sh[w][2] = s2;
        sh[w][3] = mn0; sh[w][4] = mn1; sh[w][5] = mn2;
        sh[w][6] = mx0; sh[w][7] = mx1; sh[w][8] = mx2;
    }
    __syncthreads();
    if (threadIdx.x == 0) {
        float r[9];
        #pragma unroll
        for (int j = 0; j < 9; j++) r[j] = sh[0][j];
        #pragma unroll
        for (int i = 1; i < 8; i++) {
            r[0] += sh[i][0]; r[1] += sh[i][1]; r[2] += sh[i][2];
            r[3] = fminf(r[3], sh[i][3]); r[4] = fminf(r[4], sh[i][4]);
            r[5] = fminf(r[5], sh[i][5]);
            r[6] = fmaxf(r[6], sh[i][6]); r[7] = fmaxf(r[7], sh[i][7]);
            r[8] = fmaxf(r[8], sh[i][8]);
        }
        #pragma unroll
        for (int j = 0; j < 9; j++) g_part[bid * 9 + j] = r[j];
    }
}

// ---------------- K_ln: LayerNorm, warp per row ------------------------------
__global__ void k_ln(const float* __restrict__ feats,
                     const float* __restrict__ gg, const float* __restrict__ bb) {
    int row = blockIdx.x * 8 + (threadIdx.x >> 5);
    if (row >= NPTS) return;
    int l = threadIdx.x & 31;
    float4 v = reinterpret_cast<const float4*>(feats + (size_t)row * CH)[l];
    float s = v.x + v.y + v.z + v.w;
    #pragma unroll
    for (int o = 16; o > 0; o >>= 1) s += __shfl_xor_sync(0xffffffffu, s, o);
    float mean = s * (1.0f / CH);
    float dx = v.x - mean, dy = v.y - mean, dz = v.z - mean, dw = v.w - mean;
    float q = dx * dx + dy * dy + dz * dz + dw * dw;
    #pragma unroll
    for (int o = 16; o > 0; o >>= 1) q += __shfl_xor_sync(0xffffffffu, q, o);
    float rstd = rsqrtf(q * (1.0f / CH) + 1e-5f);
    float4 g4 = reinterpret_cast<const float4*>(gg)[l];
    float4 b4 = reinterpret_cast<const float4*>(bb)[l];
    __nv_bfloat162 lo, hi;
    lo.x = __float2bfloat16(dx * rstd * g4.x + b4.x);
    lo.y = __float2bfloat16(dy * rstd * g4.y + b4.y);
    hi.x = __float2bfloat16(dz * rstd * g4.z + b4.z);
    hi.y = __float2bfloat16(dw * rstd * g4.w + b4.w);
    uint2 u;
    u.x = *reinterpret_cast<uint32_t*>(&lo);
    u.y = *reinterpret_cast<uint32_t*>(&hi);
    reinterpret_cast<uint2*>(g_xb + (size_t)row * CH)[l] = u;
}

// ---------------- K_gather: warp per point, f32x2 packed accumulate ---------
__global__ __launch_bounds__(256)
void k_gather(const float* __restrict__ pts,
              const int* __restrict__ nbr,
              const float* __restrict__ bw1, const float* __restrict__ bb1,
              const float* __restrict__ bw2, const float* __restrict__ bb2) {
    int w = threadIdx.x >> 5, l = threadIdx.x & 31;
    int n = blockIdx.x * 8 + w;
    if (n >= NPTS) return;

    int sidx = 0, vflag = 0;
    if (l < KN) {
        int v = nbr[(size_t)n * KN + l];
        vflag = (v >= 0 && v < NPTS) ? 1 : 0;
        sidx = v < 0 ? 0 : (v >= NPTS ? (NPTS - 1) : v);
    }
    unsigned ball = __ballot_sync(0xffffffffu, vflag);
    float inv = 1.0f / fmaxf((float)__popc(ball), 1.0f);

    const uint2* xb = reinterpret_cast<const uint2*>(g_xb);
    unsigned long long acc01 = 0ull, acc23 = 0ull;
    #pragma unroll
    for (int k = 0; k < KN; k++) {
        int idx = __shfl_sync(0xffffffffu, sidx, k);
        float wk = ((ball >> k) & 1u) ? 1.0f : 0.0f;
        unsigned long long wk2;
        asm("mov.b64 %0, {%1,%1};" : "=l"(wk2) : "f"(wk));
        uint2 u = xb[(size_t)idx * 32 + l];
        uint32_t f0 = u.x << 16, f1 = u.x & 0xffff0000u;
        uint32_t f2 = u.y << 16, f3 = u.y & 0xffff0000u;
        unsigned long long v01, v23;
        asm("mov.b64 %0, {%1,%2};" : "=l"(v01) : "r"(f0), "r"(f1));
        asm("mov.b64 %0, {%1,%2};" : "=l"(v23) : "r"(f2), "r"(f3));
        asm("fma.rn.f32x2 %0, %1, %2, %0;" : "+l"(acc01) : "l"(v01), "l"(wk2));
        asm("fma.rn.f32x2 %0, %1, %2, %0;" : "+l"(acc23) : "l"(v23), "l"(wk2));
    }
    float a0, a1, a2, a3;
    asm("mov.b64 {%0,%1}, %2;" : "=f"(a0), "=f"(a1) : "l"(acc01));
    asm("mov.b64 {%0,%1}, %2;" : "=f"(a2), "=f"(a3) : "l"(acc23));
    float mf0 = a0 * inv, mf1 = a1 * inv, mf2 = a2 * inv, mf3 = a3 * inv;
    {
        __nv_bfloat162 p0, p1;
        p0.x = __float2bfloat16(mf0); p0.y = __float2bfloat16(mf1);
        p1.x = __float2bfloat16(mf2); p1.y = __float2bfloat16(mf3);
        uint2 u;
        u.x = *reinterpret_cast<uint32_t*>(&p0);
        u.y = *reinterpret_cast<uint32_t*>(&p1);
        reinterpret_cast<uint2*>(g_mfb)[(size_t)n * 32 + l] = u;
    }

    uint2 xu = xb[(size_t)n * 32 + l];
    float x0 = __uint_as_float(xu.x << 16);
    float x1 = __uint_as_float(xu.x & 0xffff0000u);
    float x2 = __uint_as_float(xu.y << 16);
    float x3 = __uint_as_float(xu.y & 0xffff0000u);
    float d0 = x0 - mf0, d1 = x1 - mf1, d2 = x2 - mf2, d3 = x3 - mf3;
    float fq = d0 * d0 + d1 * d1 + d2 * d2 + d3 * d3;
    #pragma unroll
    for (int o = 16; o > 0; o >>= 1) fq += __shfl_xor_sync(0xffffffffu, fq, o);
    float fd = sqrtf(fq);

    float px = 0.f, py = 0.f, pz = 0.f;
    if (l < KN && vflag) {
        px = pts[(size_t)sidx * 3 + 0];
        py = pts[(size_t)sidx * 3 + 1];
        pz = pts[(size_t)sidx * 3 + 2];
    }
    #pragma unroll
    for (int o = 16; o > 0; o >>= 1) {
        px += __shfl_xor_sync(0xffffffffu, px, o);
        py += __shfl_xor_sync(0xffffffffu, py, o);
        pz += __shfl_xor_sync(0xffffffffu, pz, o);
    }
    float cx = pts[(size_t)n * 3 + 0] - px * inv;
    float cy = pts[(size_t)n * 3 + 1] - py * inv;
    float cz = pts[(size_t)n * 3 + 2] - pz * inv;
    float cd = sqrtf(cx * cx + cy * cy + cz * cz);

    float acc = 0.f;
    #pragma unroll
    for (int j = 0; j < 4; j++) {
        int u = l + j * 32;
        float h = gelu_fast(fd * bw1[u] + cd * bw1[CH + u] + bb1[u]);
        acc += h * bw2[u];
    }
    #pragma unroll
    for (int o = 16; o > 0; o >>= 1) acc += __shfl_xor_sync(0xffffffffu, acc, o);
    if (l == 0) g_bnd[n] = sigm(acc + bb2[0]);
}

// ---------------- mma helpers (4 warps, 32 N-cols per warp, 2 m-tiles) ------
__device__ __forceinline__ void mma16816(float (&c)[4], const uint32_t (&a)[4],
                                         uint32_t b0, uint32_t b1) {
    asm volatile(
        "mma.sync.aligned.m16n8k16.row.col.f32.bf16.bf16.f32 "
        "{%0,%1,%2,%3}, {%4,%5,%6,%7}, {%8,%9}, {%0,%1,%2,%3};\n"
        : "+f"(c[0]), "+f"(c[1]), "+f"(c[2]), "+f"(c[3])
        : "r"(a[0]), "r"(a[1]), "r"(a[2]), "r"(a[3]), "r"(b0), "r"(b1));
}

__device__ __forceinline__ void ldm4(uint32_t (&r)[4], uint32_t addr) {
    asm volatile("ldmatrix.sync.aligned.m8n8.x4.shared.b16 {%0,%1,%2,%3}, [%4];"
                 : "=r"(r[0]), "=r"(r[1]), "=r"(r[2]), "=r"(r[3]) : "r"(addr));
}

__device__ __forceinline__ void frag_init(float (&c)[2][4][4],
                                          const float* __restrict__ bias,
                                          const float* __restrict__ wb,
                                          const float* bndp,
                                          int warp, int g, int tig) {
    #pragma unroll
    for (int sub = 0; sub < 4; sub++) {
        int nA = warp * 32 + sub * 8 + tig * 2;
        float bA = bias[nA], bB = bias[nA + 1];
        float wA = wb ? wb[nA] : 0.f, wB = wb ? wb[nA + 1] : 0.f;
        #pragma unroll
        for (int mt = 0; mt < 2; mt++) {
            float e0 = bndp ? bndp[mt * 16 + g] : 0.f;
            float e8 = bndp ? bndp[mt * 16 + g + 8] : 0.f;
            c[mt][sub][0] = bA + e0 * wA;
            c[mt][sub][1] = bB + e0 * wB;
            c[mt][sub][2] = bA + e8 * wA;
            c[mt][sub][3] = bB + e8 * wB;
        }
    }
}

// A from smem via ldmatrix.x4; B from fragment-packed global (L2-resident)
__device__ __forceinline__ void gemm_acc(float (&c)[2][4][4], uint32_t abase,
                                         const uint2* __restrict__ pk,
                                         int warp, int lane) {
    int rsel = (lane & 7) + ((lane >> 3) & 1) * 8;
    int csel = (lane >> 4) * 8;
    uint32_t off0 = abase + (uint32_t)((rsel * ASTRIDE + csel) * 2);
    #pragma unroll
    for (int kk = 0; kk < 8; kk++) {
        uint32_t a[2][4];
        #pragma unroll
        for (int mt = 0; mt < 2; mt++)
            ldm4(a[mt], off0 + mt * (16 * ASTRIDE * 2) + kk * 32);
        #pragma unroll
        for (int sub = 0; sub < 4; sub++) {
            uint2 b = pk[((warp * 4 + sub) * 8 + kk) * 32 + lane];
            #pragma unroll
            for (int mt = 0; mt < 2; mt++)
                mma16816(c[mt][sub], a[mt], b.x, b.y);
        }
    }
}

__device__ __forceinline__ void frag_store(__nv_bfloat16 (*D)[ASTRIDE],
                                           const float (&c)[2][4][4], int act,
                                           int warp, int g, int tig) {
    #pragma unroll
    for (int sub = 0; sub < 4; sub++) {
        int nA = warp * 32 + sub * 8 + tig * 2;
        #pragma unroll
        for (int mt = 0; mt < 2; mt++) {
            int r = mt * 16 + g;
            float v0 = c[mt][sub][0], v1 = c[mt][sub][1];
            float v2 = c[mt][sub][2], v3 = c[mt][sub][3];
            if (act) { v0 = gelu_fast(v0); v1 = gelu_fast(v1);
                       v2 = gelu_fast(v2); v3 = gelu_fast(v3); }
            __nv_bfloat162 p01, p23;
            p01.x = __float2bfloat16(v0); p01.y = __float2bfloat16(v1);
            p23.x = __float2bfloat16(v2); p23.y = __float2bfloat16(v3);
            *reinterpret_cast<uint32_t*>(&D[r][nA])     = *reinterpret_cast<uint32_t*>(&p01);
            *reinterpret_cast<uint32_t*>(&D[r + 8][nA]) = *reinterpret_cast<uint32_t*>(&p23);
        }
    }
}

// ---------------- K_mlp: fused MLPs, BP=32, 128 thr, 4 CTA/SM ---------------
#define SMEM_ARR (BP * ASTRIDE * 2)          // 8704
#define SMEM_MLP (4 * SMEM_ARR + 256 + 768)  // xs,ms,cs,hs + bnd + cpt = 35840

__global__ __launch_bounds__(128, 4)
void k_mlp(const float* __restrict__ pts, const float* __restrict__ feats,
           const float* __restrict__ cpw1, const float* __restrict__ cpb1,
           const float* __restrict__ cpb2,
           const float* __restrict__ mw1,  const float* __restrict__ mb1,
           const float* __restrict__ mb2,
           const float* __restrict__ gw1,  const float* __restrict__ gb1,
           const float* __restrict__ gb2,
           const float* __restrict__ ob,
           float* __restrict__ out) {
    extern __shared__ char dyn[];
    __nv_bfloat16 (*xs)[ASTRIDE] = reinterpret_cast<__nv_bfloat16(*)[ASTRIDE]>(dyn);
    __nv_bfloat16 (*ms)[ASTRIDE] = reinterpret_cast<__nv_bfloat16(*)[ASTRIDE]>(dyn + SMEM_ARR);
    __nv_bfloat16 (*cs)[ASTRIDE] = reinterpret_cast<__nv_bfloat16(*)[ASTRIDE]>(dyn + 2 * SMEM_ARR);
    __nv_bfloat16 (*hs)[ASTRIDE] = reinterpret_cast<__nv_bfloat16(*)[ASTRIDE]>(dyn + 3 * SMEM_ARR);
    float* bnd       = reinterpret_cast<float*>(dyn + 4 * SMEM_ARR);
    float (*cpt)[3]  = reinterpret_cast<float(*)[3]>(dyn + 4 * SMEM_ARR + 256);
    __shared__ float sh2[4][9];
    __shared__ float s_mean[3], s_scl[3];

    int t = threadIdx.x;                 // 128 threads
    int lane = t & 31, warp = t >> 5, g = lane >> 2, tig = lane & 3;
    int p0 = blockIdx.x * BP;

    uint32_t a_xs = (uint32_t)__cvta_generic_to_shared(xs);
    uint32_t a_ms = (uint32_t)__cvta_generic_to_shared(ms);
    uint32_t a_cs = (uint32_t)__cvta_generic_to_shared(cs);
    uint32_t a_hs = (uint32_t)__cvta_generic_to_shared(hs);

    // load x / mf tiles as bf16x2 words
    {
        const uint32_t* xb32 = reinterpret_cast<const uint32_t*>(g_xb);
        const uint32_t* mb32 = reinterpret_cast<const uint32_t*>(g_mfb);
        int pair = t & 63, pr0 = t >> 6;   // 2 row-groups of 64 pairs
        #pragma unroll
        for (int p = pr0; p < BP; p += 2) {
            uint32_t vx = xb32[(size_t)(p0 + p) * 64 + pair];
            uint32_t vm = mb32[(size_t)(p0 + p) * 64 + pair];
            *reinterpret_cast<uint32_t*>(&xs[p][pair * 2]) = vx;
            *reinterpret_cast<uint32_t*>(&ms[p][pair * 2]) = vm;
        }
    }
    if (t < BP) bnd[t] = g_bnd[p0 + t];

    // combine point-stat partials (256 partials, 128 threads: 2 each)
    {
        float r[9], q[9];
        #pragma unroll
        for (int j = 0; j < 9; j++) {
            r[j] = g_part[t * 9 + j];
            q[j] = g_part[(t + 128) * 9 + j];
        }
        r[0] += q[0]; r[1] += q[1]; r[2] += q[2];
        r[3] = fminf(r[3], q[3]); r[4] = fminf(r[4], q[4]); r[5] = fminf(r[5], q[5]);
        r[6] = fmaxf(r[6], q[6]); r[7] = fmaxf(r[7], q[7]); r[8] = fmaxf(r[8], q[8]);
        #pragma unroll
        for (int o = 16; o > 0; o >>= 1) {
            r[0] += __shfl_xor_sync(0xffffffffu, r[0], o);
            r[1] += __shfl_xor_sync(0xffffffffu, r[1], o);
            r[2] += __shfl_xor_sync(0xffffffffu, r[2], o);
            r[3] = fminf(r[3], __shfl_xor_sync(0xffffffffu, r[3], o));
            r[4] = fminf(r[4], __shfl_xor_sync(0xffffffffu, r[4], o));
            r[5] = fminf(r[5], __shfl_xor_sync(0xffffffffu, r[5], o));
            r[6] = fmaxf(r[6], __shfl_xor_sync(0xffffffffu, r[6], o));
            r[7] = fmaxf(r[7], __shfl_xor_sync(0xffffffffu, r[7], o));
            r[8] = fmaxf(r[8], __shfl_xor_sync(0xffffffffu, r[8], o));
        }
        if (lane == 0)
            #pragma unroll
            for (int j = 0; j < 9; j++) sh2[warp][j] = r[j];
        __syncthreads();
        if (t == 0) {
            #pragma unroll
            for (int j = 0; j < 9; j++) r[j] = sh2[0][j];
            #pragma unroll
            for (int i = 1; i < 4; i++) {
                r[0] += sh2[i][0]; r[1] += sh2[i][1]; r[2] += sh2[i][2];
                r[3] = fminf(r[3], sh2[i][3]); r[4] = fminf(r[4], sh2[i][4]);
                r[5] = fminf(r[5], sh2[i][5]);
                r[6] = fmaxf(r[6], sh2[i][6]); r[7] = fmaxf(r[7], sh2[i][7]);
                r[8] = fmaxf(r[8], sh2[i][8]);
            }
            #pragma unroll
            for (int d = 0; d < 3; d++) {
                float mean = r[d] * (1.0f / NPTS);
                s_mean[d] = mean;
                s_scl[d]  = fmaxf(fmaxf(r[6 + d] - mean, mean - r[3 + d]), 1e-6f);
            }
        }
        __syncthreads();
    }

    if (t < BP * 3) {
        int p = t / 3, d = t - 3 * p;
        int row = min(p0 + p, NPTS - 1);
        cpt[p][d] = (pts[(size_t)row * 3 + d] - s_mean[d]) / s_scl[d];
    }
    __syncthreads();

    // coord-embed hidden (3 -> 128), SIMT: thread t owns column t
    {
        float w0 = cpw1[t], w1 = cpw1[CH + t], w2 = cpw1[2 * CH + t], b = cpb1[t];
        #pragma unroll 4
        for (int p = 0; p < BP; p++)
            hs[p][t] = __float2bfloat16(
                gelu_fast(cpt[p][0] * w0 + cpt[p][1] * w1 + cpt[p][2] * w2 + b));
    }
    __syncthreads();

    float c[2][4][4];

    // 1) coord_embed = coord_hidden @ cp_w2 + cp_b2  -> cs
    frag_init(c, cpb2, nullptr, nullptr, warp, g, tig);
    gemm_acc(c, a_hs, g_pk + 0 * 4096, warp, lane);
    frag_store(cs, c, 0, warp, g, tig);
    __syncthreads();

    // 2) mix hidden: [x | mf | bnd | ce] @ mix_w1 + b -> gelu -> hs
    frag_init(c, mb1, mw1 + 256 * CH, bnd, warp, g, tig);
    gemm_acc(c, a_xs, g_pk + 1 * 4096, warp, lane);
    gemm_acc(c, a_ms, g_pk + 2 * 4096, warp, lane);
    gemm_acc(c, a_cs, g_pk + 3 * 4096, warp, lane);
    __syncthreads();                 // everyone done reading hs (pass 1) + cs
    frag_store(hs, c, 1, warp, g, tig);

    // 3) gate hidden: [x | mf | bnd] @ gate_w1 + b -> gelu -> cs (ce dead)
    frag_init(c, gb1, gw1 + 256 * CH, bnd, warp, g, tig);
    gemm_acc(c, a_xs, g_pk + 5 * 4096, warp, lane);
    gemm_acc(c, a_ms, g_pk + 6 * 4096, warp, lane);
    __syncthreads();                 // cs reads (pass 2) done; hs stores visible
    frag_store(cs, c, 1, warp, g, tig);
    __syncthreads();

    // 4) gate = sigmoid(gate_hidden @ gate_w2 + b), packed to bf16x2 regs
    frag_init(c, gb2, nullptr, nullptr, warp, g, tig);
    gemm_acc(c, a_cs, g_pk + 7 * 4096, warp, lane);
    uint32_t ga[2][4][2];
    #pragma unroll
    for (int mt = 0; mt < 2; mt++)
        #pragma unroll
        for (int sub = 0; sub < 4; sub++) {
            __nv_bfloat162 p01, p23;
            p01.x = __float2bfloat16(sigm(c[mt][sub][0]));
            p01.y = __float2bfloat16(sigm(c[mt][sub][1]));
            p23.x = __float2bfloat16(sigm(c[mt][sub][2]));
            p23.y = __float2bfloat16(sigm(c[mt][sub][3]));
            ga[mt][sub][0] = *reinterpret_cast<uint32_t*>(&p01);
            ga[mt][sub][1] = *reinterpret_cast<uint32_t*>(&p23);
        }

    // 5) refined = mix_hidden @ mix_w2 + b;  rs = gate * refined -> xs (dead)
    frag_init(c, mb2, nullptr, nullptr, warp, g, tig);
    gemm_acc(c, a_hs, g_pk + 4 * 4096, warp, lane);
    #pragma unroll
    for (int mt = 0; mt < 2; mt++)
        #pragma unroll
        for (int sub = 0; sub < 4; sub++) {
            __nv_bfloat162 g01 = *reinterpret_cast<__nv_bfloat162*>(&ga[mt][sub][0]);
            __nv_bfloat162 g23 = *reinterpret_cast<__nv_bfloat162*>(&ga[mt][sub][1]);
            c[mt][sub][0] *= __bfloat162float(g01.x);
            c[mt][sub][1] *= __bfloat162float(g01.y);
            c[mt][sub][2] *= __bfloat162float(g23.x);
            c[mt][sub][3] *= __bfloat162float(g23.y);
        }
    __syncthreads();                 // xs reads (pass 3) done
    frag_store(xs, c, 0, warp, g, tig);
    __syncthreads();

    // 6) out = feats + rs @ out_w + out_b
    frag_init(c, ob, nullptr, nullptr, warp, g, tig);
    gemm_acc(c, a_xs, g_pk + 8 * 4096, warp, lane);
    #pragma unroll
    for (int sub = 0; sub < 4; sub++) {
        int nA = warp * 32 + sub * 8 + tig * 2;
        #pragma unroll
        for (int mt = 0; mt < 2; mt++) {
            int r = mt * 16 + g;
            int row0 = p0 + r, row8 = row0 + 8;
            if (row0 < NPTS) {
                size_t o = (size_t)row0 * CH + nA;
                float2 f = *reinterpret_cast<const float2*>(feats + o);
                float2 v; v.x = f.x + c[mt][sub][0]; v.y = f.y + c[mt][sub][1];
                *reinterpret_cast<float2*>(out + o) = v;
            }
            if (row8 < NPTS) {
                size_t o = (size_t)row8 * CH + nA;
                float2 f = *reinterpret_cast<const float2*>(feats + o);
                float2 v; v.x = f.x + c[mt][sub][2]; v.y = f.y + c[mt][sub][3];
                *reinterpret_cast<float2*>(out + o) = v;
            }
        }
    }
}

// ---------------- launch -----------------------------------------------------
extern "C" void kernel_launch(void* const* d_in, const int* in_sizes, int n_in,
                              void* d_out, int out_size) {
    const float* feats = (const float*)d_in[0];
    const float* pts   = (const float*)d_in[1];
    const int*   nbr   = (const int*)d_in[2];     // int64 downcast to int32 by harness
    const float* ln_g  = (const float*)d_in[3];
    const float* ln_b  = (const float*)d_in[4];
    const float* cpw1  = (const float*)d_in[5];
    const float* cpb1  = (const float*)d_in[6];
    const float* cpw2  = (const float*)d_in[7];
    const float* cpb2  = (const float*)d_in[8];
    const float* bw1   = (const float*)d_in[9];
    const float* bb1   = (const float*)d_in[10];
    const float* bw2   = (const float*)d_in[11];
    const float* bb2   = (const float*)d_in[12];
    const float* mw1   = (const float*)d_in[13];
    const float* mb1   = (const float*)d_in[14];
    const float* mw2   = (const float*)d_in[15];
    const float* mb2   = (const float*)d_in[16];
    const float* gw1   = (const float*)d_in[17];
    const float* gb1   = (const float*)d_in[18];
    const float* gw2   = (const float*)d_in[19];
    const float* gb2   = (const float*)d_in[20];
    const float* ow    = (const float*)d_in[21];
    const float* ob    = (const float*)d_in[22];
    float* out = (float*)d_out;

    (void)in_sizes; (void)n_in; (void)out_size;

    cudaFuncSetAttribute(k_mlp, cudaFuncAttributeMaxDynamicSharedMemorySize, SMEM_MLP);

    // 4 launches; index 3 (ncu capture slot) = k_mlp
    k_prep<<<144 + NBLK_RED, 256>>>(pts,
                                    cpw2,
                                    mw1,                 // mix rows   0..127 (x)
                                    mw1 + 128 * CH,      // mix rows 128..255 (mf)
                                    mw1 + 257 * CH,      // mix rows 257..384 (ce)
                                    mw2,
                                    gw1,                 // gate rows  0..127 (x)
                                    gw1 + 128 * CH,      // gate rows 128..255 (mf)
                                    gw2,
                                    ow);                                 // 0
    k_ln<<<(NPTS + 7) / 8, 256>>>(feats, ln_g, ln_b);                    // 1
    k_gather<<<(NPTS + 7) / 8, 256>>>(pts, nbr, bw1, bb1, bw2, bb2);     // 2
    k_mlp<<<NPAD / BP, 128, SMEM_MLP>>>(pts, feats,
                                        cpw1, cpb1, cpb2,
                                        mw1, mb1, mb2,
                                        gw1, gb1, gb2,
                                        ob, out);                        // 3
}